// round 3
// baseline (speedup 1.0000x reference)
#include <cuda_runtime.h>

#define NB 2
#define NN 192
#define NF 5
#define NSPLIT 4
#define TA 128           // threads, kernel A
#define WA 4             // warps,  kernel A
#define NG (NSPLIT*WA)   // 16 k-stride groups
#define TB 192           // threads, kernel B

__device__ float g_part[NB * NN * NSPLIT * NF];

__device__ __forceinline__ float ex2f(float x) {
    float y;
    asm("ex2.approx.ftz.f32 %0, %1;" : "=f"(y) : "f"(x));
    return y;
}

// ---------------- Kernel A: pair-loop partials ----------------
__global__ __launch_bounds__(TA)
void fa_pairs(const float* __restrict__ d, const float* __restrict__ cd,
              const float* __restrict__ fp, const float* __restrict__ coeff)
{
    const int blk  = blockIdx.x;
    const int b    = blk / (NN * NSPLIT);
    const int rem  = blk % (NN * NSPLIT);
    const int i    = rem / NSPLIT;
    const int c    = rem % NSPLIT;
    const int tid  = threadIdx.x;
    const int lane = tid & 31;
    const int w    = tid >> 5;

    __shared__ float4 sP[NN];            // (d^2, 1/(sqrt2*d), sqrt2*cd0, 0); masked at k==i
    __shared__ float  sFp[NF], sC2[NF];
    __shared__ float  sRed[WA * NF];

    if (tid < NF) {
        sFp[tid] = fp[tid];
        sC2[tid] = -144.26950408889634f * coeff[tid];  // -100*log2e*coeff
    }

    const float* __restrict__ drow  = d  + ((size_t)b * NN + i) * NN;
    const float* __restrict__ cdrow = cd + ((size_t)b * NN + i) * NN;

    for (int k = tid; k < NN; k += TA) {
        float dv = drow[k];
        float cv = cdrow[k];
        float c0 = (cv == 1.0f) ? 0.0f : cv;
        bool isI = (k == i);
        float rh = isI ? 0.0f : 0.70710678118654752f / dv;
        float wq = isI ? 0.0f : 1.41421356237309515f * c0;
        sP[k] = make_float4(dv * dv, rh, wq, 0.0f);
    }
    __syncthreads();

    float c2r[NF], mr[NF], qr[NF], acc[NF];
    #pragma unroll
    for (int f = 0; f < NF; f++) {
        float fpv = sFp[f], c2 = sC2[f];
        c2r[f] = c2;
        mr[f]  = -2.0f * c2 * fpv;
        qr[f]  = c2 * fpv * fpv;
        acc[f] = 0.0f;
    }

    const float* __restrict__ dmat = d + (size_t)b * NN * NN;
    const int g = c * WA + w;            // this warp's k-group (0..15)

    for (int k = g; k < NN; k += NG) {
        if (k == i) continue;
        float4 Pk = sP[k];
        const float D2k = Pk.x, rk = Pk.y, wk = Pk.z;
        const float* __restrict__ rowk = dmat + k * NN;

        int j = lane;
        if (j >= k) continue;
        float  dv = __ldg(rowk + j);
        float4 Pj = sP[j];

        while (true) {
            float  cur = dv;
            float4 Pc  = Pj;
            int    jn  = j + 32;
            bool   more = (jn < k);
            if (more) { dv = __ldg(rowk + jn); Pj = sP[jn]; }   // prefetch

            float num = fmaf(-cur, cur, D2k + Pc.x);   // d2j + d2k - djk^2
            float a   = (num * rk) * Pc.y;             // num / (2 d_ij d_ik)
            float a2  = a * a;
            float wgt = wk * Pc.z;                     // 2 cd0_j cd0_k

            #pragma unroll
            for (int f = 0; f < NF; f++) {
                float arg = fmaf(c2r[f], a2, fmaf(mr[f], a, qr[f]));
                acc[f] = fmaf(ex2f(arg), wgt, acc[f]);
            }

            if (!more) break;
            j = jn;
        }
    }

    #pragma unroll
    for (int f = 0; f < NF; f++) {
        #pragma unroll
        for (int o = 16; o; o >>= 1)
            acc[f] += __shfl_down_sync(0xFFFFFFFFu, acc[f], o);
    }
    if (lane == 0) {
        #pragma unroll
        for (int f = 0; f < NF; f++) sRed[w * NF + f] = acc[f];
    }
    __syncthreads();

    if (tid < NF) {
        float t = 0.f;
        #pragma unroll
        for (int wi = 0; wi < WA; wi++) t += sRed[wi * NF + tid];
        g_part[blk * NF + tid] = t;
    }
}

// ------- Kernel B: analytic terms + combine partials -> out -------
__global__ __launch_bounds__(TB)
void fa_final(const float* __restrict__ cd,
              const float* __restrict__ fp, const float* __restrict__ coeff,
              float* __restrict__ out)
{
    const int b    = blockIdx.x / NN;
    const int i    = blockIdx.x % NN;
    const int tid  = threadIdx.x;
    const int lane = tid & 31;
    const int w    = tid >> 5;

    __shared__ float sS[TB / 32], sSS[TB / 32];
    __shared__ float sCdii;

    const float* __restrict__ cdrow = cd + ((size_t)b * NN + i) * NN;

    float cv = cdrow[tid];                    // tid < 192 == NN
    float c0 = (cv == 1.0f) ? 0.0f : cv;
    if (tid == i) sCdii = c0;
    float pS = c0, pSS = c0 * c0;
    #pragma unroll
    for (int o = 16; o; o >>= 1) {
        pS  += __shfl_down_sync(0xFFFFFFFFu, pS,  o);
        pSS += __shfl_down_sync(0xFFFFFFFFu, pSS, o);
    }
    if (lane == 0) { sS[w] = pS; sSS[w] = pSS; }
    __syncthreads();

    if (tid < NF) {
        float S = 0.f, SS = 0.f;
        #pragma unroll
        for (int wi = 0; wi < TB / 32; wi++) { S += sS[wi]; SS += sSS[wi]; }
        float cii = sCdii;
        float fpv = fp[tid];
        float c2v = -144.26950408889634f * coeff[tid];
        float g0  = ex2f((c2v * fpv) * fpv);            // a = 0 (j==i or k==i)
        float d1  = 1.0f - fpv;
        float g1  = ex2f((c2v * d1) * d1);              // a = 1 (diag j==k!=i)
        float t = g0 * cii * (2.0f * S - cii) + g1 * (SS - cii * cii);
        int base = (blockIdx.x) * NSPLIT * NF;
        #pragma unroll
        for (int s = 0; s < NSPLIT; s++) t += g_part[base + s * NF + tid];
        out[blockIdx.x * NF + tid] = t * (1.0f / (NN * 12));
    }
}

extern "C" void kernel_launch(void* const* d_in, const int* in_sizes, int n_in,
                              void* d_out, int out_size)
{
    const float* d     = (const float*)d_in[0];   // (B,N,N)
    const float* cd    = (const float*)d_in[1];   // (B,N,N)
    const float* fp    = (const float*)d_in[2];   // (5,)
    const float* coeff = (const float*)d_in[3];   // (5,)
    float* out = (float*)d_out;                   // (B,N,5)

    fa_pairs<<<NB * NN * NSPLIT, TA>>>(d, cd, fp, coeff);
    fa_final<<<NB * NN, TB>>>(cd, fp, coeff, out);
}

// round 4
// speedup vs baseline: 1.0219x; 1.0219x over previous
#include <cuda_runtime.h>

#define NB 2
#define NN 192
#define NF 5
#define THREADS 256
#define NWARP 8

__device__ __forceinline__ float ex2f(float x) {
    float y;
    asm("ex2.approx.ftz.f32 %0, %1;" : "=f"(y) : "f"(x));
    return y;
}

__global__ __launch_bounds__(THREADS)
void fa_kernel(const float* __restrict__ d, const float* __restrict__ cd,
               const float* __restrict__ fp, const float* __restrict__ coeff,
               float* __restrict__ out)
{
    const int b    = blockIdx.x / NN;
    const int i    = blockIdx.x % NN;
    const int tid  = threadIdx.x;
    const int lane = tid & 31;
    const int w    = tid >> 5;

    __shared__ float4 sP[NN];        // (d^2, 1/(sqrt2*d), sqrt2*cd0, 0); zeroed at k==i
    __shared__ float  sFp[NF], sC2[NF];
    __shared__ float  sRed[NWARP * NF];
    __shared__ float  sS[NWARP], sSS[NWARP];
    __shared__ float  sCdii;

    if (tid < NF) {
        sFp[tid] = fp[tid];
        sC2[tid] = -144.26950408889634f * coeff[tid];   // -100*log2(e)*coeff
    }

    const float* __restrict__ drow  = d  + ((size_t)b * NN + i) * NN;
    const float* __restrict__ cdrow = cd + ((size_t)b * NN + i) * NN;

    // ---- Phase 1: per-k precompute + partial sums of cd0, cd0^2 ----
    float pS = 0.f, pSS = 0.f;
    if (tid < NN) {
        float dv = drow[tid];
        float cv = cdrow[tid];
        float c0 = (cv == 1.0f) ? 0.0f : cv;
        pS  = c0;
        pSS = c0 * c0;
        bool isI = (tid == i);
        float rh = isI ? 0.0f : 0.70710678118654752f / dv;
        float wq = isI ? 0.0f : 1.41421356237309515f * c0;
        sP[tid] = make_float4(dv * dv, rh, wq, 0.0f);
        if (isI) sCdii = c0;
    }
    #pragma unroll
    for (int o = 16; o; o >>= 1) {
        pS  += __shfl_down_sync(0xFFFFFFFFu, pS,  o);
        pSS += __shfl_down_sync(0xFFFFFFFFu, pSS, o);
    }
    if (lane == 0) { sS[w] = pS; sSS[w] = pSS; }
    __syncthreads();

    float c2r[NF], mr[NF], qr[NF], acc[NF];
    #pragma unroll
    for (int f = 0; f < NF; f++) {
        float fpv = sFp[f], c2 = sC2[f];
        c2r[f] = c2;
        mr[f]  = -2.0f * c2 * fpv;
        qr[f]  = c2 * fpv * fpv;
        acc[f] = 0.0f;
    }

    // ---- Phase 2: strictly-lower triangle; warp w owns rows k ≡ w (mod 8).
    // Branchless: k==i row and j==i entries zeroed via sP masks; lanes with
    // j>=k masked via wgt select. Cross-row software pipeline: next row's
    // head LDG + sP[k] issued while current row drains.
    const float* __restrict__ dmat = d + (size_t)b * NN * NN;

    const float4 Pj0 = sP[lane];                 // first-chunk table entry, row-invariant

    int    kcur = w;
    float  dv   = __ldg(dmat + kcur * NN + lane);   // prologue: row w head
    float4 Pk   = sP[kcur];

    while (kcur < NN) {
        const int   knext   = kcur + NWARP;
        const bool  hasNext = knext < NN;
        const float D2k = Pk.x, rk = Pk.y, wk = Pk.z;
        const float* __restrict__ rowk = dmat + kcur * NN;

        // prefetch next row's head immediately (covers L2 latency under this row's math)
        float  dvN = 0.f;
        float4 PkN = Pj0;   // dummy init
        if (hasNext) {
            dvN = __ldg(dmat + knext * NN + lane);
            PkN = sP[knext];
        }

        int    j    = lane;
        float  dcur = dv;
        float4 Pc   = Pj0;

        while (true) {
            int  jn   = j + 32;
            bool more = jn < kcur;
            float  dnx = 0.f;
            float4 Pnx;
            if (more) { dnx = __ldg(rowk + jn); Pnx = sP[jn]; }   // in-row prefetch

            float num = fmaf(-dcur, dcur, D2k + Pc.x);   // d2j + d2k - djk^2
            float a   = (num * rk) * Pc.y;               // num / (2 d_ij d_ik)
            float a2  = a * a;
            float wgt = (j < kcur) ? wk * Pc.z : 0.0f;   // 2 cd0_j cd0_k, tail-masked

            #pragma unroll
            for (int f = 0; f < NF; f++) {
                float arg = fmaf(c2r[f], a2, fmaf(mr[f], a, qr[f]));
                acc[f] = fmaf(ex2f(arg), wgt, acc[f]);
            }

            if (!more) break;
            j = jn; dcur = dnx; Pc = Pnx;
        }

        kcur = knext;
        dv   = dvN;
        Pk   = PkN;
    }

    // ---- Reduce 5 accumulators ----
    #pragma unroll
    for (int f = 0; f < NF; f++) {
        #pragma unroll
        for (int o = 16; o; o >>= 1)
            acc[f] += __shfl_down_sync(0xFFFFFFFFu, acc[f], o);
    }
    if (lane == 0) {
        #pragma unroll
        for (int f = 0; f < NF; f++) sRed[w * NF + f] = acc[f];
    }
    __syncthreads();

    if (tid < NF) {
        float t = 0.f;
        #pragma unroll
        for (int wi = 0; wi < NWARP; wi++) t += sRed[wi * NF + tid];
        float S = 0.f, SS = 0.f;
        #pragma unroll
        for (int wi = 0; wi < NWARP; wi++) { S += sS[wi]; SS += sSS[wi]; }
        float cii = sCdii;
        float fpv = sFp[tid], c2v = sC2[tid];
        float g0 = ex2f((c2v * fpv) * fpv);        // a = 0 terms (j==i or k==i)
        float d1 = 1.0f - fpv;
        float g1 = ex2f((c2v * d1) * d1);          // a = 1 terms (diagonal j==k!=i)
        t += g0 * cii * (2.0f * S - cii) + g1 * (SS - cii * cii);
        out[blockIdx.x * NF + tid] = t * (1.0f / (NN * 12));
    }
}

extern "C" void kernel_launch(void* const* d_in, const int* in_sizes, int n_in,
                              void* d_out, int out_size)
{
    const float* d     = (const float*)d_in[0];   // (B,N,N)
    const float* cd    = (const float*)d_in[1];   // (B,N,N)
    const float* fp    = (const float*)d_in[2];   // (5,)
    const float* coeff = (const float*)d_in[3];   // (5,)
    float* out = (float*)d_out;                   // (B,N,5)

    fa_kernel<<<NB * NN, THREADS>>>(d, cd, fp, coeff, out);
}

// round 5
// speedup vs baseline: 1.4009x; 1.3709x over previous
#include <cuda_runtime.h>

#define NB 2
#define NN 192
#define NF 5
#define THREADS 256
#define NWARP 8
#define NTILE (NN/4)     // 48 tiles of 4 rows

__device__ __forceinline__ float ex2f(float x) {
    float y;
    asm("ex2.approx.ftz.f32 %0, %1;" : "=f"(y) : "f"(x));
    return y;
}

__global__ __launch_bounds__(THREADS)
void fa_kernel(const float* __restrict__ d, const float* __restrict__ cd,
               const float* __restrict__ fp, const float* __restrict__ coeff,
               float* __restrict__ out)
{
    const int b    = blockIdx.x / NN;
    const int i    = blockIdx.x % NN;
    const int tid  = threadIdx.x;
    const int lane = tid & 31;
    const int w    = tid >> 5;

    __shared__ float4 sP[NN];        // (d^2, 1/(sqrt2*d), sqrt2*cd0, 0); zeroed at ==i
    __shared__ float  sFp[NF], sC2[NF];
    __shared__ float  sRed[NWARP * NF];
    __shared__ float  sS[NWARP], sSS[NWARP];
    __shared__ float  sCdii;

    if (tid < NF) {
        sFp[tid] = fp[tid];
        sC2[tid] = -144.26950408889634f * coeff[tid];   // -100*log2(e)*coeff
    }

    const float* __restrict__ drow  = d  + ((size_t)b * NN + i) * NN;
    const float* __restrict__ cdrow = cd + ((size_t)b * NN + i) * NN;

    // ---- Phase 1: per-k precompute + partial sums of cd0, cd0^2 ----
    float pS = 0.f, pSS = 0.f;
    if (tid < NN) {
        float dv = drow[tid];
        float cv = cdrow[tid];
        float c0 = (cv == 1.0f) ? 0.0f : cv;
        pS  = c0;
        pSS = c0 * c0;
        bool isI = (tid == i);
        float rh = isI ? 0.0f : 0.70710678118654752f / dv;
        float wq = isI ? 0.0f : 1.41421356237309515f * c0;
        sP[tid] = make_float4(dv * dv, rh, wq, 0.0f);
        if (isI) sCdii = c0;
    }
    #pragma unroll
    for (int o = 16; o; o >>= 1) {
        pS  += __shfl_down_sync(0xFFFFFFFFu, pS,  o);
        pSS += __shfl_down_sync(0xFFFFFFFFu, pSS, o);
    }
    if (lane == 0) { sS[w] = pS; sSS[w] = pSS; }
    __syncthreads();

    float c2r[NF], mr[NF], qr[NF], acc[NF];
    #pragma unroll
    for (int f = 0; f < NF; f++) {
        float fpv = sFp[f], c2 = sC2[f];
        c2r[f] = c2;
        mr[f]  = -2.0f * c2 * fpv;
        qr[f]  = c2 * fpv * fpv;
        acc[f] = 0.0f;
    }

    // ---- Phase 2: 4-row register-blocked triangle sweep ----
    // Warp w owns row-tiles t ≡ w (mod 8); tile t = rows k0..k0+3, k0 = 4t.
    // Pairs (j, k), j < k; rows/cols ==i contribute 0 via masked tables.
    const float* __restrict__ dmat = d + (size_t)b * NN * NN;

    for (int t = w; t < NTILE; t += NWARP) {
        const int k0 = t << 2;

        float4 Pk[4];
        const float* __restrict__ rp[4];
        #pragma unroll
        for (int q = 0; q < 4; q++) {
            Pk[q] = sP[k0 + q];
            rp[q] = dmat + (size_t)(k0 + q) * NN;
        }

        const int T = (k0 + 34) >> 5;   // iterations: covers j <= k0+2
        const int F = k0 >> 5;          // iterations m < F are fully inside triangle

        // prefetch m = 0
        float  dv[4];
        #pragma unroll
        for (int q = 0; q < 4; q++) dv[q] = __ldg(rp[q] + lane);
        float4 Pj = sP[lane];

        for (int m = 0; m < T; m++) {
            float  ev[4];
            #pragma unroll
            for (int q = 0; q < 4; q++) ev[q] = dv[q];
            float4 Pc = Pj;
            const int jc = lane + (m << 5);

            if (m + 1 < T) {                      // prefetch next chunk
                const int jn = jc + 32;
                #pragma unroll
                for (int q = 0; q < 4; q++) dv[q] = __ldg(rp[q] + jn);
                Pj = sP[jn];
            }

            float av[4], a2v[4], wv[4];
            #pragma unroll
            for (int q = 0; q < 4; q++) {
                float num = fmaf(-ev[q], ev[q], Pk[q].x + Pc.x);
                float a   = (num * Pc.y) * Pk[q].y;
                av[q]  = a;
                a2v[q] = a * a;
                wv[q]  = Pk[q].z * Pc.z;
            }
            if (m >= F) {                         // warp-uniform: mask triangle tail
                #pragma unroll
                for (int q = 0; q < 4; q++)
                    wv[q] = (jc < k0 + q) ? wv[q] : 0.0f;
            }

            #pragma unroll
            for (int q = 0; q < 4; q++) {
                #pragma unroll
                for (int f = 0; f < NF; f++) {
                    float arg = fmaf(c2r[f], a2v[q], fmaf(mr[f], av[q], qr[f]));
                    acc[f] = fmaf(ex2f(arg), wv[q], acc[f]);
                }
            }
        }
    }

    // ---- Reduce 5 accumulators ----
    #pragma unroll
    for (int f = 0; f < NF; f++) {
        #pragma unroll
        for (int o = 16; o; o >>= 1)
            acc[f] += __shfl_down_sync(0xFFFFFFFFu, acc[f], o);
    }
    if (lane == 0) {
        #pragma unroll
        for (int f = 0; f < NF; f++) sRed[w * NF + f] = acc[f];
    }
    __syncthreads();

    if (tid < NF) {
        float tacc = 0.f;
        #pragma unroll
        for (int wi = 0; wi < NWARP; wi++) tacc += sRed[wi * NF + tid];
        float S = 0.f, SS = 0.f;
        #pragma unroll
        for (int wi = 0; wi < NWARP; wi++) { S += sS[wi]; SS += sSS[wi]; }
        float cii = sCdii;
        float fpv = sFp[tid], c2v = sC2[tid];
        float g0 = ex2f((c2v * fpv) * fpv);        // a = 0 terms (j==i or k==i)
        float d1 = 1.0f - fpv;
        float g1 = ex2f((c2v * d1) * d1);          // a = 1 terms (diagonal j==k!=i)
        tacc += g0 * cii * (2.0f * S - cii) + g1 * (SS - cii * cii);
        out[blockIdx.x * NF + tid] = tacc * (1.0f / (NN * 12));
    }
}

extern "C" void kernel_launch(void* const* d_in, const int* in_sizes, int n_in,
                              void* d_out, int out_size)
{
    const float* d     = (const float*)d_in[0];   // (B,N,N)
    const float* cd    = (const float*)d_in[1];   // (B,N,N)
    const float* fp    = (const float*)d_in[2];   // (5,)
    const float* coeff = (const float*)d_in[3];   // (5,)
    float* out = (float*)d_out;                   // (B,N,5)

    fa_kernel<<<NB * NN, THREADS>>>(d, cd, fp, coeff, out);
}